// round 14
// baseline (speedup 1.0000x reference)
#include <cuda_runtime.h>
#include <math.h>

#define Hh   16
#define DU   64
#define DP   32
#define Dd   96
#define Bn   16
#define TCACHE 4095
#define TT   4096
#define WIN  512
#define Fdim 1536

#define SPLIT  2
#define ROWS_B (WIN / SPLIT)      // 256 rows per stream CTA
#define ITER_B (ROWS_B / 8 / 4)   // 8 iterations per warp (8 warps, 4 rows/iter)

__device__ float g_qt[Bn * Hh][104];            // [0..95]=qt, [96]=const
__device__ float g_pl[Bn * Hh * SPLIT];         // partial l
__device__ float g_pacc[Bn * Hh * SPLIT][Dd];   // partial acc

// ---------------- Kernel A: q projection + K-fold ----------------
__global__ __launch_bounds__(128)
void prep_kernel(const float* __restrict__ content,
                 const float* __restrict__ Wq_u, const float* __restrict__ bq_u,
                 const float* __restrict__ Wk_u, const float* __restrict__ bk_u,
                 const float* __restrict__ Wq_p, const float* __restrict__ bq_p,
                 const float* __restrict__ Wk_p, const float* __restrict__ bk_p)
{
    const int h   = blockIdx.x;
    const int b   = blockIdx.y;
    const int tid = threadIdx.x;

    __shared__ float s_u[Dd];
    __shared__ float s_q[Dd];

    const float* crow = content + (size_t)b * Fdim + h * Dd;
    if (tid < Dd) s_u[tid] = crow[tid];
    __syncthreads();

    if (tid < DU) {
        const float* Wc = Wq_u + ((size_t)h * DU) * DU + tid;
        float acc = bq_u[h * DU + tid];
        #pragma unroll 8
        for (int d = 0; d < DU; d++) acc = fmaf(s_u[d], Wc[d * DU], acc);
        s_q[tid] = acc;
    } else if (tid < Dd) {
        int e = tid - DU;
        const float* Wc = Wq_p + ((size_t)h * DP) * DP + e;
        float acc = bq_p[h * DP + e];
        #pragma unroll 8
        for (int d = 0; d < DP; d++) acc = fmaf(s_u[DU + d], Wc[d * DP], acc);
        s_q[tid] = acc;
    }
    __syncthreads();

    const float inv = 1.0f / sqrtf((float)Dd);
    float* qt = g_qt[b * Hh + h];
    if (tid < DU) {
        const float4* Wr = (const float4*)(Wk_u + ((size_t)h * DU + tid) * DU);
        float acc = 0.f;
        #pragma unroll
        for (int e4 = 0; e4 < DU / 4; e4++) {
            float4 wv = Wr[e4];
            acc += wv.x * s_q[e4*4] + wv.y * s_q[e4*4+1] + wv.z * s_q[e4*4+2] + wv.w * s_q[e4*4+3];
        }
        qt[tid] = acc * inv;
    } else if (tid < Dd) {
        int d = tid - DU;
        const float4* Wr = (const float4*)(Wk_p + ((size_t)h * DP + d) * DP);
        float acc = 0.f;
        #pragma unroll
        for (int e4 = 0; e4 < DP / 4; e4++) {
            float4 wv = Wr[e4];
            acc += wv.x * s_q[DU+e4*4] + wv.y * s_q[DU+e4*4+1] + wv.z * s_q[DU+e4*4+2] + wv.w * s_q[DU+e4*4+3];
        }
        qt[tid] = acc * inv;
    } else if (tid == Dd) {
        float acc = 0.f;
        for (int e = 0; e < DU; e++) acc = fmaf(s_q[e],      bk_u[h * DU + e], acc);
        for (int e = 0; e < DP; e++) acc = fmaf(s_q[DU + e], bk_p[h * DP + e], acc);
        qt[Dd] = acc * inv;
    }
}

// ---------------- Kernel B: streaming attention over a window split ----------------
__global__ __launch_bounds__(256, 4)
void stream_kernel(const float* __restrict__ content,
                   const float* __restrict__ cache,
                   const float* __restrict__ pos_param_p)
{
    const int h     = blockIdx.x;
    const int b     = blockIdx.y;
    const int split = blockIdx.z;
    const int tid   = threadIdx.x;
    const int lane  = tid & 31;
    const int w     = tid >> 5;
    const int qq    = lane >> 3;
    const int s     = lane & 7;
    const int s4    = s * 4;

    __shared__ alignas(16) float s_qt[104];
    __shared__ float s_bias[ROWS_B];
    __shared__ float s_gl[32];
    __shared__ alignas(16) float s_gacc[32][Dd];

    const float pp = *pos_param_p;

    if (tid < 97) s_qt[tid] = g_qt[b * Hh + h][tid];

    // bias for this split's rows (time_mask is a uniform shift -> ignored)
    for (int p = tid; p < ROWS_B; p += 256) {
        int n = (WIN - 1) - (split * ROWS_B + p);
        float bucket;
        if (n < 16)        bucket = (float)n;
        else if (n >= 113) bucket = 31.0f;
        else {
            int bb = 16 + (int)(__logf((float)n * 0.0625f) * 7.69365658f);
            bucket = (float)bb;
        }
        s_bias[p] = -pp * bucket;
    }
    __syncthreads();

    const float4* q4 = (const float4*)s_qt;
    const float4  qtA = q4[s], qtB = q4[8 + s], qtC = q4[16 + s];
    const float   sc  = s_qt[Dd];
    const float*  crow  = content + (size_t)b * Fdim + h * Dd;
    const float*  cbase = cache   + ((size_t)b * TCACHE) * Fdim + h * Dd;
    const int     base  = (TT - WIN) + split * ROWS_B + w * (ROWS_B / 8);

    float l = 0.f;
    float4 aA = {0,0,0,0}, aB = {0,0,0,0}, aC = {0,0,0,0};

    const float* r0;
    {
        int j = base + qq;
        r0 = (j < TCACHE) ? (cbase + (size_t)j * Fdim) : crow;
    }
    float4 nva = *(const float4*)(r0 + s4);
    float4 nvb = *(const float4*)(r0 + 32 + s4);
    float4 nvc = *(const float4*)(r0 + 64 + s4);

    #pragma unroll 2
    for (int i = 0; i < ITER_B; i++) {
        float4 va = nva, vb = nvb, vc = nvc;
        if (i < ITER_B - 1) {
            int j = base + (i + 1) * 4 + qq;
            const float* r = (j < TCACHE) ? (cbase + (size_t)j * Fdim) : crow;
            nva = *(const float4*)(r + s4);
            nvb = *(const float4*)(r + 32 + s4);
            nvc = *(const float4*)(r + 64 + s4);
        }
        float x;
        x = va.x * qtA.x;          x = fmaf(va.y, qtA.y, x);
        x = fmaf(va.z, qtA.z, x);  x = fmaf(va.w, qtA.w, x);
        x = fmaf(vb.x, qtB.x, x);  x = fmaf(vb.y, qtB.y, x);
        x = fmaf(vb.z, qtB.z, x);  x = fmaf(vb.w, qtB.w, x);
        x = fmaf(vc.x, qtC.x, x);  x = fmaf(vc.y, qtC.y, x);
        x = fmaf(vc.z, qtC.z, x);  x = fmaf(vc.w, qtC.w, x);
        x += __shfl_xor_sync(0xffffffffu, x, 1);
        x += __shfl_xor_sync(0xffffffffu, x, 2);
        x += __shfl_xor_sync(0xffffffffu, x, 4);

        float e = __expf(x + sc + s_bias[w * (ROWS_B / 8) + i * 4 + qq]);
        l += e;
        aA.x = fmaf(e, va.x, aA.x); aA.y = fmaf(e, va.y, aA.y);
        aA.z = fmaf(e, va.z, aA.z); aA.w = fmaf(e, va.w, aA.w);
        aB.x = fmaf(e, vb.x, aB.x); aB.y = fmaf(e, vb.y, aB.y);
        aB.z = fmaf(e, vb.z, aB.z); aB.w = fmaf(e, vb.w, aB.w);
        aC.x = fmaf(e, vc.x, aC.x); aC.y = fmaf(e, vc.y, aC.y);
        aC.z = fmaf(e, vc.z, aC.z); aC.w = fmaf(e, vc.w, aC.w);
    }

    const int g = (w << 2) | qq;
    if (s == 0) s_gl[g] = l;
    *(float4*)&s_gacc[g][s4]      = aA;
    *(float4*)&s_gacc[g][32 + s4] = aB;
    *(float4*)&s_gacc[g][64 + s4] = aC;
    __syncthreads();

    const int bh = (b * Hh + h) * SPLIT + split;
    if (tid < Dd) {
        float a = 0.f;
        #pragma unroll
        for (int gg = 0; gg < 32; gg++) a += s_gacc[gg][tid];
        g_pacc[bh][tid] = a;
    } else if (tid == Dd) {
        float L = 0.f;
        #pragma unroll
        for (int gg = 0; gg < 32; gg++) L += s_gl[gg];
        g_pl[bh] = L;
    }
}

// ---------------- Kernel C: combine + V-projection + residual ----------------
__global__ __launch_bounds__(128)
void combine_kernel(const float* __restrict__ content,
                    const float* __restrict__ Wv_u, const float* __restrict__ bv_u,
                    const float* __restrict__ Wv_p, const float* __restrict__ bv_p,
                    float* __restrict__ out)
{
    const int h   = blockIdx.x;
    const int b   = blockIdx.y;
    const int tid = threadIdx.x;

    __shared__ float s_cbar[Dd];

    const int bh0 = (b * Hh + h) * SPLIT;
    if (tid < Dd) {
        float a = 0.f, L = 0.f;
        #pragma unroll
        for (int sp = 0; sp < SPLIT; sp++) {
            a += g_pacc[bh0 + sp][tid];
            if (tid == 0) {}
        }
        #pragma unroll
        for (int sp = 0; sp < SPLIT; sp++) L += g_pl[bh0 + sp];
        s_cbar[tid] = a / L;
    }
    __syncthreads();

    const float* crow = content + (size_t)b * Fdim + h * Dd;
    if (tid < DU) {
        const float* Wc = Wv_u + ((size_t)h * DU) * DU + tid;
        float acc = bv_u[h * DU + tid];
        #pragma unroll 8
        for (int d = 0; d < DU; d++) acc = fmaf(s_cbar[d], Wc[d * DU], acc);
        out[(size_t)b * Fdim + h * Dd + tid] = acc + crow[tid];
    } else if (tid < Dd) {
        int e = tid - DU;
        const float* Wc = Wv_p + ((size_t)h * DP) * DP + e;
        float acc = bv_p[h * DP + e];
        #pragma unroll 8
        for (int d = 0; d < DP; d++) acc = fmaf(s_cbar[DU + d], Wc[d * DP], acc);
        out[(size_t)b * Fdim + h * Dd + tid] = acc + crow[tid];
    }
}

extern "C" void kernel_launch(void* const* d_in, const int* in_sizes, int n_in,
                              void* d_out, int out_size)
{
    const float* content = (const float*)d_in[1];
    const float* cache   = (const float*)d_in[3];
    const float* Wq_u    = (const float*)d_in[5];
    const float* bq_u    = (const float*)d_in[6];
    const float* Wk_u    = (const float*)d_in[7];
    const float* bk_u    = (const float*)d_in[8];
    const float* Wv_u    = (const float*)d_in[9];
    const float* bv_u    = (const float*)d_in[10];
    const float* Wq_p    = (const float*)d_in[11];
    const float* bq_p    = (const float*)d_in[12];
    const float* Wk_p    = (const float*)d_in[13];
    const float* bk_p    = (const float*)d_in[14];
    const float* Wv_p    = (const float*)d_in[15];
    const float* bv_p    = (const float*)d_in[16];
    const float* pos_p   = (const float*)d_in[17];
    float* out = (float*)d_out;

    dim3 gridA(Hh, Bn);
    prep_kernel<<<gridA, 128>>>(content, Wq_u, bq_u, Wk_u, bk_u,
                                Wq_p, bq_p, Wk_p, bk_p);

    dim3 gridB(Hh, Bn, SPLIT);
    stream_kernel<<<gridB, 256>>>(content, cache, pos_p);

    dim3 gridC(Hh, Bn);
    combine_kernel<<<gridC, 128>>>(content, Wv_u, bv_u, Wv_p, bv_p, out);
}